// round 9
// baseline (speedup 1.0000x reference)
#include <cuda_runtime.h>
#include <cuda_bf16.h>
#include <cstdint>
#include <math.h>

typedef unsigned int u32;

#define D_MODEL 1024
#define NH 16
#define DK 64
#define BATCH 2
#define SEQ 2048
#define M_ROWS (BATCH * SEQ)   // 4096

#define NEG_INF (__int_as_float(0xff800000))

// ---------------------------------------------------------------------------
// Scratch (__device__ globals; no allocs allowed)
// ---------------------------------------------------------------------------
__device__ float g_QKV[(size_t)M_ROWS * 3 * D_MODEL];

__device__ __nv_bfloat16 g_xhi[(size_t)M_ROWS * D_MODEL];
__device__ __nv_bfloat16 g_xlo[(size_t)M_ROWS * D_MODEL];
__device__ __nv_bfloat16 g_ahi[(size_t)M_ROWS * D_MODEL];
__device__ __nv_bfloat16 g_alo[(size_t)M_ROWS * D_MODEL];
__device__ __nv_bfloat16 g_whi[4ull * D_MODEL * D_MODEL];
__device__ __nv_bfloat16 g_wlo[4ull * D_MODEL * D_MODEL];

#define HM_ELEMS ((size_t)BATCH * NH * SEQ * DK)
__device__ __nv_bfloat16 g_qh[HM_ELEMS];
__device__ __nv_bfloat16 g_ql[HM_ELEMS];
__device__ __nv_bfloat16 g_kh[HM_ELEMS];
__device__ __nv_bfloat16 g_kl[HM_ELEMS];
__device__ __nv_bfloat16 g_vh[HM_ELEMS];
__device__ __nv_bfloat16 g_vl[HM_ELEMS];

// ---------------------------------------------------------------------------
// helpers
// ---------------------------------------------------------------------------
__device__ __forceinline__ void split2(float a, float b,
                                       __nv_bfloat162* hp, __nv_bfloat162* lp)
{
    __nv_bfloat162 h = __floats2bfloat162_rn(a, b);
    float2 hf = __bfloat1622float2(h);
    *hp = h;
    *lp = __floats2bfloat162_rn(a - hf.x, b - hf.y);
}

__device__ __forceinline__ void ldsm_x4(u32* r, const __nv_bfloat16* p)
{
    u32 a = (u32)__cvta_generic_to_shared(p);
    asm volatile("ldmatrix.sync.aligned.m8n8.x4.shared.b16 {%0,%1,%2,%3}, [%4];"
        : "=r"(r[0]), "=r"(r[1]), "=r"(r[2]), "=r"(r[3]) : "r"(a));
}

__device__ __forceinline__ void ldsm_x2(u32* r, const __nv_bfloat16* p)
{
    u32 a = (u32)__cvta_generic_to_shared(p);
    asm volatile("ldmatrix.sync.aligned.m8n8.x2.shared.b16 {%0,%1}, [%2];"
        : "=r"(r[0]), "=r"(r[1]) : "r"(a));
}

__device__ __forceinline__ void ldsm_x2t(u32* r, const __nv_bfloat16* p)
{
    u32 a = (u32)__cvta_generic_to_shared(p);
    asm volatile("ldmatrix.sync.aligned.m8n8.x2.trans.shared.b16 {%0,%1}, [%2];"
        : "=r"(r[0]), "=r"(r[1]) : "r"(a));
}

__device__ __forceinline__ void mma16816(float* d, const u32* a, const u32* b)
{
    asm volatile("mma.sync.aligned.m16n8k16.row.col.f32.bf16.bf16.f32 "
        "{%0,%1,%2,%3}, {%4,%5,%6,%7}, {%8,%9}, {%0,%1,%2,%3};"
        : "+f"(d[0]), "+f"(d[1]), "+f"(d[2]), "+f"(d[3])
        : "r"(a[0]), "r"(a[1]), "r"(a[2]), "r"(a[3]), "r"(b[0]), "r"(b[1]));
}

__device__ __forceinline__ void cp_async16(u32 smem_addr, const void* gptr)
{
    asm volatile("cp.async.cg.shared.global [%0], [%1], 16;"
        :: "r"(smem_addr), "l"(gptr));
}

__device__ __forceinline__ void cp_commit()
{
    asm volatile("cp.async.commit_group;");
}

__device__ __forceinline__ void cp_wait1()
{
    asm volatile("cp.async.wait_group 1;");
}

// ---------------------------------------------------------------------------
// Splits
// ---------------------------------------------------------------------------
__global__ void split_bf16(const float* __restrict__ in,
                           __nv_bfloat16* __restrict__ hi,
                           __nv_bfloat16* __restrict__ lo, int n4)
{
    int i = blockIdx.x * blockDim.x + threadIdx.x;
    if (i >= n4) return;
    float4 v = ((const float4*)in)[i];
    __nv_bfloat162 h0, l0, h1, l1;
    split2(v.x, v.y, &h0, &l0);
    split2(v.z, v.w, &h1, &l1);
    __nv_bfloat162* hp = (__nv_bfloat162*)(hi + 4 * (size_t)i);
    __nv_bfloat162* lp = (__nv_bfloat162*)(lo + 4 * (size_t)i);
    hp[0] = h0;
    hp[1] = h1;
    lp[0] = l0;
    lp[1] = l1;
}

// all 4 weights in one launch; blockIdx.y picks the weight
__global__ void split_w4(const float* __restrict__ W0, const float* __restrict__ W1,
                         const float* __restrict__ W2, const float* __restrict__ W3,
                         __nv_bfloat16* __restrict__ hi,
                         __nv_bfloat16* __restrict__ lo, int n4)
{
    int i = blockIdx.x * blockDim.x + threadIdx.x;
    if (i >= n4) return;
    int wsel = blockIdx.y;
    const float* W = (wsel == 0) ? W0 : (wsel == 1) ? W1 : (wsel == 2) ? W2 : W3;
    size_t off = (size_t)wsel * D_MODEL * D_MODEL;
    float4 v = ((const float4*)W)[i];
    __nv_bfloat162 h0, l0, h1, l1;
    split2(v.x, v.y, &h0, &l0);
    split2(v.z, v.w, &h1, &l1);
    __nv_bfloat162* hp = (__nv_bfloat162*)(hi + off + 4 * (size_t)i);
    __nv_bfloat162* lp = (__nv_bfloat162*)(lo + off + 4 * (size_t)i);
    hp[0] = h0;
    hp[1] = h1;
    lp[0] = l0;
    lp[1] = l1;
}

// ---------------------------------------------------------------------------
// Pipelined tensor-core GEMM: C[M,N] = A[M,K] * B[N,K]^T, 3-pass hi/lo split.
// 128x128 tile, BK=32, cp.async 2-stage double buffer, dynamic smem.
// ---------------------------------------------------------------------------
#define BM 128
#define BN 128
#define BKT 32
#define LDT 40
#define G_ARR (BM * LDT)               // 5120 elems per array
#define G_STAGE (4 * G_ARR)            // elems per stage
#define G_ARR_B (G_ARR * 2)            // 10240 bytes per array
#define G_SMEM_BYTES (2 * G_STAGE * 2) // 81920

__global__ void __launch_bounds__(256) gemm_mma_split(
    const __nv_bfloat16* __restrict__ Ahi, const __nv_bfloat16* __restrict__ Alo,
    const __nv_bfloat16* __restrict__ Bhi, const __nv_bfloat16* __restrict__ Blo,
    float* __restrict__ C, int M, int N, int K)
{
    extern __shared__ __align__(16) __nv_bfloat16 dyn[];

    const int tid  = threadIdx.x;
    const int lane = tid & 31;
    const int warp = tid >> 5;
    const int m0 = blockIdx.y * BM;
    const int n0 = blockIdx.x * BN;
    const int wm = (warp & 1) * 64;
    const int wn = (warp >> 1) * 32;

    float acc[4][4][4];
#pragma unroll
    for (int mt = 0; mt < 4; mt++) {
#pragma unroll
        for (int nt = 0; nt < 4; nt++) {
#pragma unroll
            for (int q = 0; q < 4; q++) {
                acc[mt][nt][q] = 0.f;
            }
        }
    }

    auto load_stage = [&](int stg, int k0) {
        __nv_bfloat16* st = dyn + stg * G_STAGE;
#pragma unroll
        for (int p = 0; p < 2; p++) {
            int idx = tid + p * 256;
            int r = idx >> 2;
            int c = (idx & 3) * 8;
            u32 d = (u32)__cvta_generic_to_shared(st + r * LDT + c);
            cp_async16(d,               &Ahi[(size_t)(m0 + r) * K + k0 + c]);
            cp_async16(d + 1 * G_ARR_B, &Alo[(size_t)(m0 + r) * K + k0 + c]);
            cp_async16(d + 2 * G_ARR_B, &Bhi[(size_t)(n0 + r) * K + k0 + c]);
            cp_async16(d + 3 * G_ARR_B, &Blo[(size_t)(n0 + r) * K + k0 + c]);
        }
    };

    const int nk = K / BKT;
    load_stage(0, 0);
    cp_commit();

    for (int kt = 0; kt < nk; kt++) {
        if (kt + 1 < nk) {
            load_stage((kt + 1) & 1, (kt + 1) * BKT);
        }
        cp_commit();
        cp_wait1();
        __syncthreads();

        const __nv_bfloat16* st = dyn + (kt & 1) * G_STAGE;
        const __nv_bfloat16* pAhi = st;
        const __nv_bfloat16* pAlo = st + 1 * G_ARR;
        const __nv_bfloat16* pBhi = st + 2 * G_ARR;
        const __nv_bfloat16* pBlo = st + 3 * G_ARR;

#pragma unroll
        for (int ks = 0; ks < 2; ks++) {
            const int kk = ks * 16;
            u32 ah[4][4];
            u32 al[4][4];
            u32 bh[4][2];
            u32 bl[4][2];
#pragma unroll
            for (int mt = 0; mt < 4; mt++) {
                const int rr = wm + mt * 16 + (lane & 15);
                const int cc = kk + (lane >> 4) * 8;
                ldsm_x4(ah[mt], pAhi + rr * LDT + cc);
                ldsm_x4(al[mt], pAlo + rr * LDT + cc);
            }
#pragma unroll
            for (int nt = 0; nt < 4; nt++) {
                const int rr = wn + nt * 8 + (lane & 7);
                const int cc = kk + ((lane >> 3) & 1) * 8;
                ldsm_x2(bh[nt], pBhi + rr * LDT + cc);
                ldsm_x2(bl[nt], pBlo + rr * LDT + cc);
            }
#pragma unroll
            for (int mt = 0; mt < 4; mt++) {
#pragma unroll
                for (int nt = 0; nt < 4; nt++) {
                    mma16816(acc[mt][nt], ah[mt], bh[nt]);
                    mma16816(acc[mt][nt], ah[mt], bl[nt]);
                    mma16816(acc[mt][nt], al[mt], bh[nt]);
                }
            }
        }
        __syncthreads();
    }

#pragma unroll
    for (int mt = 0; mt < 4; mt++) {
#pragma unroll
        for (int nt = 0; nt < 4; nt++) {
            const int row = m0 + wm + mt * 16 + (lane >> 2);
            const int col = n0 + wn + nt * 8 + (lane & 3) * 2;
            float2 v0;
            v0.x = acc[mt][nt][0];
            v0.y = acc[mt][nt][1];
            float2 v1;
            v1.x = acc[mt][nt][2];
            v1.y = acc[mt][nt][3];
            *(float2*)&C[(size_t)row * N + col] = v0;
            *(float2*)&C[(size_t)(row + 8) * N + col] = v1;
        }
    }
}

// ---------------------------------------------------------------------------
// qkv_finish: RoPE + hi/lo split + head-major relayout.
// ---------------------------------------------------------------------------
__global__ void qkv_finish(const float* __restrict__ QKV,
                           __nv_bfloat16* __restrict__ qh, __nv_bfloat16* __restrict__ ql,
                           __nv_bfloat16* __restrict__ kh, __nv_bfloat16* __restrict__ kl,
                           __nv_bfloat16* __restrict__ vh, __nv_bfloat16* __restrict__ vl)
{
    int idx = blockIdx.x * blockDim.x + threadIdx.x;
    if (idx >= M_ROWS * (D_MODEL / 2)) return;
    int row = idx >> 9;
    int p   = idx & 511;
    int h = p >> 5;
    int i = p & 31;
    int s = row & (SEQ - 1);
    int b = row >> 11;

    float freq = powf(10000.0f, -((float)(2 * i) / (float)DK));
    float ang = (float)s * freq;
    float c = cosf(ang);
    float sn = sinf(ang);

    size_t src = (size_t)row * (3 * D_MODEL) + h * DK + 2 * i;
    float q1 = QKV[src];
    float q2 = QKV[src + 1];
    float k1 = QKV[src + D_MODEL];
    float k2 = QKV[src + D_MODEL + 1];
    float v1 = QKV[src + 2 * D_MODEL];
    float v2 = QKV[src + 2 * D_MODEL + 1];

    float rq1 = (q1 * c - q2 * sn) * 0.125f;
    float rq2 = (q1 * sn + q2 * c) * 0.125f;
    float rk1 = k1 * c - k2 * sn;
    float rk2 = k1 * sn + k2 * c;

    size_t dst = ((size_t)(b * NH + h) * SEQ + s) * DK + 2 * i;
    __nv_bfloat162 h2, l2;
    split2(rq1, rq2, &h2, &l2);
    *(__nv_bfloat162*)&qh[dst] = h2;
    *(__nv_bfloat162*)&ql[dst] = l2;
    split2(rk1, rk2, &h2, &l2);
    *(__nv_bfloat162*)&kh[dst] = h2;
    *(__nv_bfloat162*)&kl[dst] = l2;
    split2(v1, v2, &h2, &l2);
    *(__nv_bfloat162*)&vh[dst] = h2;
    *(__nv_bfloat162*)&vl[dst] = l2;
}

// ---------------------------------------------------------------------------
// MMA flash attention, cp.async 2-stage KV pipeline.
// CTA = 64 q rows x one (h,b). 4 warps, 16 rows each.
// ---------------------------------------------------------------------------
#define A_LD 72
#define A_ARR (64 * A_LD)                 // 4608 elems
#define A_STAGE (4 * A_ARR)               // elems per stage
#define A_ARR_B (A_ARR * 2)               // 9216 bytes
#define A_SMEM_BYTES (2 * A_STAGE * 2)    // 73728

__global__ void __launch_bounds__(128) attn_mma(
    const __nv_bfloat16* __restrict__ qh_, const __nv_bfloat16* __restrict__ ql_,
    const __nv_bfloat16* __restrict__ kh_, const __nv_bfloat16* __restrict__ kl_,
    const __nv_bfloat16* __restrict__ vh_, const __nv_bfloat16* __restrict__ vl_,
    __nv_bfloat16* __restrict__ ohi, __nv_bfloat16* __restrict__ olo)
{
    extern __shared__ __align__(16) __nv_bfloat16 dynA[];

    const int qt = blockIdx.x;
    const int hb = blockIdx.y;
    const int t = threadIdx.x;
    const int lane = t & 31;
    const int w = t >> 5;
    const size_t base = (size_t)hb * (SEQ * DK);
    const int q0 = qt * 64;

    // stage Q (hi/lo) in stage0's first two arrays, extract fragments
    for (int i = t; i < 512; i += 128) {
        int r = i >> 3, c = (i & 7) * 8;
        *(uint4*)(dynA + r * A_LD + c) =
            *(const uint4*)&qh_[base + (size_t)(q0 + r) * DK + c];
        *(uint4*)(dynA + A_ARR + r * A_LD + c) =
            *(const uint4*)&ql_[base + (size_t)(q0 + r) * DK + c];
    }
    __syncthreads();

    u32 qfh[4][4];
    u32 qfl[4][4];
#pragma unroll
    for (int kc = 0; kc < 4; kc++) {
        const int rr = w * 16 + (lane & 15);
        const int cc = kc * 16 + (lane >> 4) * 8;
        ldsm_x4(qfh[kc], dynA + rr * A_LD + cc);
        ldsm_x4(qfl[kc], dynA + A_ARR + rr * A_LD + cc);
    }
    __syncthreads();   // Q fragments extracted; smem reusable

    auto load_kv = [&](int stg, int k0r) {
        __nv_bfloat16* st = dynA + stg * A_STAGE;
#pragma unroll
        for (int i = t; i < 512; i += 128) {
            int r = i >> 3, c = (i & 7) * 8;
            size_t g = base + (size_t)(k0r + r) * DK + c;
            u32 d = (u32)__cvta_generic_to_shared(st + r * A_LD + c);
            cp_async16(d,               &kh_[g]);
            cp_async16(d + 1 * A_ARR_B, &kl_[g]);
            cp_async16(d + 2 * A_ARR_B, &vh_[g]);
            cp_async16(d + 3 * A_ARR_B, &vl_[g]);
        }
    };

    float m0 = NEG_INF, m1 = NEG_INF, l0 = 0.f, l1 = 0.f;
    float O[8][4];
#pragma unroll
    for (int nt = 0; nt < 8; nt++) {
#pragma unroll
        for (int q = 0; q < 4; q++) O[nt][q] = 0.f;
    }

    load_kv(0, 0);
    cp_commit();

    for (int jt = 0; jt <= qt; jt++) {
        if (jt + 1 <= qt) {
            load_kv((jt + 1) & 1, (jt + 1) * 64);
        }
        cp_commit();
        cp_wait1();
        __syncthreads();

        const __nv_bfloat16* st = dynA + (jt & 1) * A_STAGE;
        const __nv_bfloat16* pKh = st;
        const __nv_bfloat16* pKl = st + 1 * A_ARR;
        const __nv_bfloat16* pVh = st + 2 * A_ARR;
        const __nv_bfloat16* pVl = st + 3 * A_ARR;

        // S = Q @ K^T (3-pass split)
        float S[8][4];
#pragma unroll
        for (int nt = 0; nt < 8; nt++) {
#pragma unroll
            for (int q = 0; q < 4; q++) S[nt][q] = 0.f;
        }
#pragma unroll
        for (int nt = 0; nt < 8; nt++) {
#pragma unroll
            for (int kc = 0; kc < 4; kc++) {
                u32 kbh[2], kbl[2];
                const int rr = nt * 8 + (lane & 7);
                const int cc = kc * 16 + ((lane >> 3) & 1) * 8;
                ldsm_x2(kbh, pKh + rr * A_LD + cc);
                ldsm_x2(kbl, pKl + rr * A_LD + cc);
                mma16816(S[nt], qfh[kc], kbh);
                mma16816(S[nt], qfh[kc], kbl);
                mma16816(S[nt], qfl[kc], kbh);
            }
        }

        // causal mask + row max
        const bool diag = (jt == qt);
        const int rowm = w * 16 + (lane >> 2);
        float tm0 = NEG_INF, tm1 = NEG_INF;
#pragma unroll
        for (int nt = 0; nt < 8; nt++) {
            const int cn = nt * 8 + (lane & 3) * 2;
            if (diag) {
                if (cn > rowm)         S[nt][0] = NEG_INF;
                if (cn + 1 > rowm)     S[nt][1] = NEG_INF;
                if (cn > rowm + 8)     S[nt][2] = NEG_INF;
                if (cn + 1 > rowm + 8) S[nt][3] = NEG_INF;
            }
            tm0 = fmaxf(tm0, fmaxf(S[nt][0], S[nt][1]));
            tm1 = fmaxf(tm1, fmaxf(S[nt][2], S[nt][3]));
        }
        tm0 = fmaxf(tm0, __shfl_xor_sync(0xffffffffu, tm0, 1));
        tm0 = fmaxf(tm0, __shfl_xor_sync(0xffffffffu, tm0, 2));
        tm1 = fmaxf(tm1, __shfl_xor_sync(0xffffffffu, tm1, 1));
        tm1 = fmaxf(tm1, __shfl_xor_sync(0xffffffffu, tm1, 2));

        const float mn0 = fmaxf(m0, tm0);
        const float mn1 = fmaxf(m1, tm1);
        const float a0 = __expf(m0 - mn0);
        const float a1 = __expf(m1 - mn1);

        float ps0 = 0.f, ps1 = 0.f;
#pragma unroll
        for (int nt = 0; nt < 8; nt++) {
            S[nt][0] = __expf(S[nt][0] - mn0);
            S[nt][1] = __expf(S[nt][1] - mn0);
            S[nt][2] = __expf(S[nt][2] - mn1);
            S[nt][3] = __expf(S[nt][3] - mn1);
            ps0 += S[nt][0] + S[nt][1];
            ps1 += S[nt][2] + S[nt][3];
        }
        ps0 += __shfl_xor_sync(0xffffffffu, ps0, 1);
        ps0 += __shfl_xor_sync(0xffffffffu, ps0, 2);
        ps1 += __shfl_xor_sync(0xffffffffu, ps1, 1);
        ps1 += __shfl_xor_sync(0xffffffffu, ps1, 2);
        l0 = l0 * a0 + ps0;
        l1 = l1 * a1 + ps1;
#pragma unroll
        for (int nt = 0; nt < 8; nt++) {
            O[nt][0] *= a0;
            O[nt][1] *= a0;
            O[nt][2] *= a1;
            O[nt][3] *= a1;
        }
        m0 = mn0;
        m1 = mn1;

        // O += P @ V (3-pass split)
#pragma unroll
        for (int kc = 0; kc < 4; kc++) {
            u32 ph[4], pl[4];
            __nv_bfloat162 h2, l2;
            split2(S[2 * kc][0], S[2 * kc][1], &h2, &l2);
            ph[0] = *(u32*)&h2;
            pl[0] = *(u32*)&l2;
            split2(S[2 * kc][2], S[2 * kc][3], &h2, &l2);
            ph[1] = *(u32*)&h2;
            pl[1] = *(u32*)&l2;
            split2(S[2 * kc + 1][0], S[2 * kc + 1][1], &h2, &l2);
            ph[2] = *(u32*)&h2;
            pl[2] = *(u32*)&l2;
            split2(S[2 * kc + 1][2], S[2 * kc + 1][3], &h2, &l2);
            ph[3] = *(u32*)&h2;
            pl[3] = *(u32*)&l2;
#pragma unroll
            for (int nt = 0; nt < 8; nt++) {
                u32 vbh[2], vbl[2];
                const int rr = kc * 16 + (lane & 15);
                ldsm_x2t(vbh, pVh + rr * A_LD + nt * 8);
                ldsm_x2t(vbl, pVl + rr * A_LD + nt * 8);
                mma16816(O[nt], ph, vbh);
                mma16816(O[nt], ph, vbl);
                mma16816(O[nt], pl, vbh);
            }
        }
        __syncthreads();
    }

    // epilogue
    const float i0 = 1.0f / l0;
    const float i1 = 1.0f / l1;
    const int h = hb & (NH - 1);
    const int b = hb >> 4;
    const int s0 = q0 + w * 16 + (lane >> 2);
    const size_t r0 = (size_t)(b * SEQ + s0) * D_MODEL + h * DK + (lane & 3) * 2;
    const size_t r1 = r0 + 8ull * D_MODEL;
#pragma unroll
    for (int nt = 0; nt < 8; nt++) {
        __nv_bfloat162 h2, l2;
        split2(O[nt][0] * i0, O[nt][1] * i0, &h2, &l2);
        *(__nv_bfloat162*)&ohi[r0 + nt * 8] = h2;
        *(__nv_bfloat162*)&olo[r0 + nt * 8] = l2;
        split2(O[nt][2] * i1, O[nt][3] * i1, &h2, &l2);
        *(__nv_bfloat162*)&ohi[r1 + nt * 8] = h2;
        *(__nv_bfloat162*)&olo[r1 + nt * 8] = l2;
    }
}

// ---------------------------------------------------------------------------
extern "C" void kernel_launch(void* const* d_in, const int* in_sizes, int n_in,
                              void* d_out, int out_size)
{
    const float* x  = (const float*)d_in[0];
    const float* Wq = (const float*)d_in[1];
    const float* Wk = (const float*)d_in[2];
    const float* Wv = (const float*)d_in[3];
    const float* Wo = (const float*)d_in[4];
    float* out = (float*)d_out;

    float* qkv = 0;
    cudaGetSymbolAddress((void**)&qkv, g_QKV);

    __nv_bfloat16* xhi = 0;
    __nv_bfloat16* xlo = 0;
    __nv_bfloat16* ahi = 0;
    __nv_bfloat16* alo = 0;
    __nv_bfloat16* whi = 0;
    __nv_bfloat16* wlo = 0;
    cudaGetSymbolAddress((void**)&xhi, g_xhi);
    cudaGetSymbolAddress((void**)&xlo, g_xlo);
    cudaGetSymbolAddress((void**)&ahi, g_ahi);
    cudaGetSymbolAddress((void**)&alo, g_alo);
    cudaGetSymbolAddress((void**)&whi, g_whi);
    cudaGetSymbolAddress((void**)&wlo, g_wlo);

    __nv_bfloat16* qh = 0;
    __nv_bfloat16* ql = 0;
    __nv_bfloat16* kh = 0;
    __nv_bfloat16* kl = 0;
    __nv_bfloat16* vh = 0;
    __nv_bfloat16* vl = 0;
    cudaGetSymbolAddress((void**)&qh, g_qh);
    cudaGetSymbolAddress((void**)&ql, g_ql);
    cudaGetSymbolAddress((void**)&kh, g_kh);
    cudaGetSymbolAddress((void**)&kl, g_kl);
    cudaGetSymbolAddress((void**)&vh, g_vh);
    cudaGetSymbolAddress((void**)&vl, g_vl);

    const size_t WSZ = (size_t)D_MODEL * D_MODEL;
    const int wN4 = (int)(WSZ / 4);
    const int xN4 = M_ROWS * D_MODEL / 4;
    const int wBlocks = (wN4 + 255) / 256;
    const int xBlocks = (xN4 + 255) / 256;

    cudaFuncSetAttribute(gemm_mma_split,
                         cudaFuncAttributeMaxDynamicSharedMemorySize, G_SMEM_BYTES);
    cudaFuncSetAttribute(attn_mma,
                         cudaFuncAttributeMaxDynamicSharedMemorySize, A_SMEM_BYTES);

    dim3 wgrid(wBlocks, 4);
    split_w4<<<wgrid, 256>>>(Wq, Wk, Wv, Wo, whi, wlo, wN4);
    split_bf16<<<xBlocks, 256>>>(x, xhi, xlo, xN4);

    // fused QKV projection: C[4096][3072] = x @ [Wq;Wk;Wv]^T
    dim3 gqkv(3 * D_MODEL / BN, M_ROWS / BM);
    gemm_mma_split<<<gqkv, 256, G_SMEM_BYTES>>>(xhi, xlo, whi, wlo, qkv,
                                                M_ROWS, 3 * D_MODEL, D_MODEL);

    int npairs = M_ROWS * (D_MODEL / 2);
    qkv_finish<<<(npairs + 255) / 256, 256>>>(qkv, qh, ql, kh, kl, vh, vl);

    dim3 agrid(SEQ / 64, NH * BATCH);
    attn_mma<<<agrid, 128, A_SMEM_BYTES>>>(qh, ql, kh, kl, vh, vl, ahi, alo);

    dim3 go(D_MODEL / BN, M_ROWS / BM);
    gemm_mma_split<<<go, 256, G_SMEM_BYTES>>>(ahi, alo, whi + 3 * WSZ, wlo + 3 * WSZ,
                                              out, M_ROWS, D_MODEL, D_MODEL);
}

// round 11
// speedup vs baseline: 1.3966x; 1.3966x over previous
#include <cuda_runtime.h>
#include <cuda_fp16.h>
#include <cstdint>
#include <math.h>

typedef unsigned int u32;

#define D_MODEL 1024
#define NH 16
#define DK 64
#define BATCH 2
#define SEQ 2048
#define M_ROWS (BATCH * SEQ)   // 4096

#define NEG_INF (__int_as_float(0xff800000))

// ---------------------------------------------------------------------------
// Scratch (__device__ globals; no allocs allowed)
// ---------------------------------------------------------------------------
__device__ float g_QKV[(size_t)M_ROWS * 3 * D_MODEL];

__device__ __half g_xh[(size_t)M_ROWS * D_MODEL];      // x hi
__device__ __half g_xl[(size_t)M_ROWS * D_MODEL];      // x lo
__device__ __half g_ah[(size_t)M_ROWS * D_MODEL];      // attn out hi
__device__ __half g_al[(size_t)M_ROWS * D_MODEL];      // attn out lo
__device__ __half g_wh[4ull * D_MODEL * D_MODEL];      // weights single fp16

#define HM_ELEMS ((size_t)BATCH * NH * SEQ * DK)
__device__ __half g_qh[HM_ELEMS];                      // Q hi (A-side: split)
__device__ __half g_ql[HM_ELEMS];                      // Q lo
__device__ __half g_kh[HM_ELEMS];                      // K single (B-side)
__device__ __half g_vh[HM_ELEMS];                      // V single (B-side)

// ---------------------------------------------------------------------------
// helpers
// ---------------------------------------------------------------------------
__device__ __forceinline__ void split2h(float a, float b, u32* hp, u32* lp)
{
    __half2 h = __floats2half2_rn(a, b);
    float2 hf = __half22float2(h);
    __half2 l = __floats2half2_rn(a - hf.x, b - hf.y);
    *hp = *(u32*)&h;
    *lp = *(u32*)&l;
}

__device__ __forceinline__ void ldsm_x4(u32* r, const __half* p)
{
    u32 a = (u32)__cvta_generic_to_shared(p);
    asm volatile("ldmatrix.sync.aligned.m8n8.x4.shared.b16 {%0,%1,%2,%3}, [%4];"
        : "=r"(r[0]), "=r"(r[1]), "=r"(r[2]), "=r"(r[3]) : "r"(a));
}

__device__ __forceinline__ void ldsm_x2(u32* r, const __half* p)
{
    u32 a = (u32)__cvta_generic_to_shared(p);
    asm volatile("ldmatrix.sync.aligned.m8n8.x2.shared.b16 {%0,%1}, [%2];"
        : "=r"(r[0]), "=r"(r[1]) : "r"(a));
}

__device__ __forceinline__ void ldsm_x2t(u32* r, const __half* p)
{
    u32 a = (u32)__cvta_generic_to_shared(p);
    asm volatile("ldmatrix.sync.aligned.m8n8.x2.trans.shared.b16 {%0,%1}, [%2];"
        : "=r"(r[0]), "=r"(r[1]) : "r"(a));
}

__device__ __forceinline__ void mma16816(float* d, const u32* a, const u32* b)
{
    asm volatile("mma.sync.aligned.m16n8k16.row.col.f32.f16.f16.f32 "
        "{%0,%1,%2,%3}, {%4,%5,%6,%7}, {%8,%9}, {%0,%1,%2,%3};"
        : "+f"(d[0]), "+f"(d[1]), "+f"(d[2]), "+f"(d[3])
        : "r"(a[0]), "r"(a[1]), "r"(a[2]), "r"(a[3]), "r"(b[0]), "r"(b[1]));
}

// ---------------------------------------------------------------------------
// Splits / converts
// ---------------------------------------------------------------------------
__global__ void split_x(const float* __restrict__ in,
                        __half* __restrict__ hi, __half* __restrict__ lo, int n4)
{
    int i = blockIdx.x * blockDim.x + threadIdx.x;
    if (i >= n4) return;
    float4 v = ((const float4*)in)[i];
    u32 h0, l0, h1, l1;
    split2h(v.x, v.y, &h0, &l0);
    split2h(v.z, v.w, &h1, &l1);
    u32* hp = (u32*)(hi + 4 * (size_t)i);
    u32* lp = (u32*)(lo + 4 * (size_t)i);
    hp[0] = h0;
    hp[1] = h1;
    lp[0] = l0;
    lp[1] = l1;
}

// all 4 weights converted to single fp16 in one launch
__global__ void convert_w4(const float* __restrict__ W0, const float* __restrict__ W1,
                           const float* __restrict__ W2, const float* __restrict__ W3,
                           __half* __restrict__ out, int n4)
{
    int i = blockIdx.x * blockDim.x + threadIdx.x;
    if (i >= n4) return;
    int wsel = blockIdx.y;
    const float* W = (wsel == 0) ? W0 : (wsel == 1) ? W1 : (wsel == 2) ? W2 : W3;
    size_t off = (size_t)wsel * D_MODEL * D_MODEL;
    float4 v = ((const float4*)W)[i];
    __half2 h0 = __floats2half2_rn(v.x, v.y);
    __half2 h1 = __floats2half2_rn(v.z, v.w);
    u32* hp = (u32*)(out + off + 4 * (size_t)i);
    hp[0] = *(u32*)&h0;
    hp[1] = *(u32*)&h1;
}

// ---------------------------------------------------------------------------
// 2-pass fp16 GEMM: C[M,N] = (Ahi+Alo)[M,K] * B[N,K]^T, fp32 out.
// 128x128 tile, BK=32, 8 warps (2m x 4n), warp tile 64x32 (m16n8k16).
// Static smem, no cp.async (R8 showed pipelining doesn't help here).
// ---------------------------------------------------------------------------
#define BM 128
#define BN 128
#define BKT 32
#define LDT 40

__global__ void __launch_bounds__(256) gemm_2p(
    const __half* __restrict__ Ahi, const __half* __restrict__ Alo,
    const __half* __restrict__ B,
    float* __restrict__ C, int M, int N, int K)
{
    __shared__ __align__(16) __half sAh[BM][LDT];
    __shared__ __align__(16) __half sAl[BM][LDT];
    __shared__ __align__(16) __half sB[BN][LDT];

    const int tid  = threadIdx.x;
    const int lane = tid & 31;
    const int warp = tid >> 5;
    const int m0 = blockIdx.y * BM;
    const int n0 = blockIdx.x * BN;
    const int wm = (warp & 1) * 64;
    const int wn = (warp >> 1) * 32;

    float acc[4][4][4];
#pragma unroll
    for (int mt = 0; mt < 4; mt++) {
#pragma unroll
        for (int nt = 0; nt < 4; nt++) {
#pragma unroll
            for (int q = 0; q < 4; q++) {
                acc[mt][nt][q] = 0.f;
            }
        }
    }

    for (int k0 = 0; k0 < K; k0 += BKT) {
#pragma unroll
        for (int p = 0; p < 2; p++) {
            int idx = tid + p * 256;
            int r = idx >> 2;
            int c = (idx & 3) * 8;
            *(uint4*)&sAh[r][c] = *(const uint4*)&Ahi[(size_t)(m0 + r) * K + k0 + c];
            *(uint4*)&sAl[r][c] = *(const uint4*)&Alo[(size_t)(m0 + r) * K + k0 + c];
            *(uint4*)&sB[r][c]  = *(const uint4*)&B[(size_t)(n0 + r) * K + k0 + c];
        }
        __syncthreads();

#pragma unroll
        for (int ks = 0; ks < 2; ks++) {
            const int kk = ks * 16;
            u32 ah[4][4];
            u32 al[4][4];
            u32 bh[4][2];
#pragma unroll
            for (int mt = 0; mt < 4; mt++) {
                const int rr = wm + mt * 16 + (lane & 15);
                const int cc = kk + (lane >> 4) * 8;
                ldsm_x4(ah[mt], &sAh[rr][cc]);
                ldsm_x4(al[mt], &sAl[rr][cc]);
            }
#pragma unroll
            for (int nt = 0; nt < 4; nt++) {
                const int rr = wn + nt * 8 + (lane & 7);
                const int cc = kk + ((lane >> 3) & 1) * 8;
                ldsm_x2(bh[nt], &sB[rr][cc]);
            }
#pragma unroll
            for (int mt = 0; mt < 4; mt++) {
#pragma unroll
                for (int nt = 0; nt < 4; nt++) {
                    mma16816(acc[mt][nt], ah[mt], bh[nt]);
                    mma16816(acc[mt][nt], al[mt], bh[nt]);
                }
            }
        }
        __syncthreads();
    }

#pragma unroll
    for (int mt = 0; mt < 4; mt++) {
#pragma unroll
        for (int nt = 0; nt < 4; nt++) {
            const int row = m0 + wm + mt * 16 + (lane >> 2);
            const int col = n0 + wn + nt * 8 + (lane & 3) * 2;
            float2 v0;
            v0.x = acc[mt][nt][0];
            v0.y = acc[mt][nt][1];
            float2 v1;
            v1.x = acc[mt][nt][2];
            v1.y = acc[mt][nt][3];
            *(float2*)&C[(size_t)row * N + col] = v0;
            *(float2*)&C[(size_t)(row + 8) * N + col] = v1;
        }
    }
}

// ---------------------------------------------------------------------------
// qkv_finish: RoPE + fp16 convert/split + head-major relayout.
// Q -> hi/lo split (A-side of QK mma); K, V -> single fp16 (B-side).
// ---------------------------------------------------------------------------
__global__ void qkv_finish(const float* __restrict__ QKV,
                           __half* __restrict__ qh, __half* __restrict__ ql,
                           __half* __restrict__ kh, __half* __restrict__ vh)
{
    int idx = blockIdx.x * blockDim.x + threadIdx.x;
    if (idx >= M_ROWS * (D_MODEL / 2)) return;
    int row = idx >> 9;
    int p   = idx & 511;
    int h = p >> 5;
    int i = p & 31;
    int s = row & (SEQ - 1);
    int b = row >> 11;

    float freq = powf(10000.0f, -((float)(2 * i) / (float)DK));
    float ang = (float)s * freq;
    float c = cosf(ang);
    float sn = sinf(ang);

    size_t src = (size_t)row * (3 * D_MODEL) + h * DK + 2 * i;
    float q1 = QKV[src];
    float q2 = QKV[src + 1];
    float k1 = QKV[src + D_MODEL];
    float k2 = QKV[src + D_MODEL + 1];
    float v1 = QKV[src + 2 * D_MODEL];
    float v2 = QKV[src + 2 * D_MODEL + 1];

    float rq1 = (q1 * c - q2 * sn) * 0.125f;
    float rq2 = (q1 * sn + q2 * c) * 0.125f;
    float rk1 = k1 * c - k2 * sn;
    float rk2 = k1 * sn + k2 * c;

    size_t dst = ((size_t)(b * NH + h) * SEQ + s) * DK + 2 * i;
    u32 h2, l2;
    split2h(rq1, rq2, &h2, &l2);
    *(u32*)&qh[dst] = h2;
    *(u32*)&ql[dst] = l2;
    __half2 kk = __floats2half2_rn(rk1, rk2);
    *(u32*)&kh[dst] = *(u32*)&kk;
    __half2 vv = __floats2half2_rn(v1, v2);
    *(u32*)&vh[dst] = *(u32*)&vv;
}

// ---------------------------------------------------------------------------
// MMA flash attention, 2-pass fp16. CTA = 64 q rows x one (h,b).
// 4 warps, 16 rows each. K/V single fp16 in smem; Q and P split hi/lo.
// ---------------------------------------------------------------------------
__global__ void __launch_bounds__(128) attn_mma(
    const __half* __restrict__ qh_, const __half* __restrict__ ql_,
    const __half* __restrict__ kh_, const __half* __restrict__ vh_,
    __half* __restrict__ ohi, __half* __restrict__ olo)
{
    __shared__ __align__(16) __half sK[64][72];
    __shared__ __align__(16) __half sV[64][72];

    const int qt = blockIdx.x;
    const int hb = blockIdx.y;
    const int t = threadIdx.x;
    const int lane = t & 31;
    const int w = t >> 5;
    const size_t base = (size_t)hb * (SEQ * DK);
    const int q0 = qt * 64;

    // stage Q hi into sK, Q lo into sV; extract A fragments
    for (int i = t; i < 512; i += 128) {
        int r = i >> 3, c = (i & 7) * 8;
        *(uint4*)&sK[r][c] = *(const uint4*)&qh_[base + (size_t)(q0 + r) * DK + c];
        *(uint4*)&sV[r][c] = *(const uint4*)&ql_[base + (size_t)(q0 + r) * DK + c];
    }
    __syncthreads();

    u32 qfh[4][4];
    u32 qfl[4][4];
#pragma unroll
    for (int kc = 0; kc < 4; kc++) {
        const int rr = w * 16 + (lane & 15);
        const int cc = kc * 16 + (lane >> 4) * 8;
        ldsm_x4(qfh[kc], &sK[rr][cc]);
        ldsm_x4(qfl[kc], &sV[rr][cc]);
    }

    float m0 = NEG_INF, m1 = NEG_INF, l0 = 0.f, l1 = 0.f;
    float O[8][4];
#pragma unroll
    for (int nt = 0; nt < 8; nt++) {
#pragma unroll
        for (int q = 0; q < 4; q++) O[nt][q] = 0.f;
    }

    for (int jt = 0; jt <= qt; jt++) {
        const int k0r = jt * 64;
        __syncthreads();
        for (int i = t; i < 512; i += 128) {
            int r = i >> 3, c = (i & 7) * 8;
            size_t g = base + (size_t)(k0r + r) * DK + c;
            *(uint4*)&sK[r][c] = *(const uint4*)&kh_[g];
            *(uint4*)&sV[r][c] = *(const uint4*)&vh_[g];
        }
        __syncthreads();

        // S = Q @ K^T (2 passes: hi, lo)
        float S[8][4];
#pragma unroll
        for (int nt = 0; nt < 8; nt++) {
#pragma unroll
            for (int q = 0; q < 4; q++) S[nt][q] = 0.f;
        }
#pragma unroll
        for (int nt = 0; nt < 8; nt++) {
#pragma unroll
            for (int kc = 0; kc < 4; kc++) {
                u32 kb[2];
                const int rr = nt * 8 + (lane & 7);
                const int cc = kc * 16 + ((lane >> 3) & 1) * 8;
                ldsm_x2(kb, &sK[rr][cc]);
                mma16816(S[nt], qfh[kc], kb);
                mma16816(S[nt], qfl[kc], kb);
            }
        }

        // causal mask + online softmax
        const bool diag = (jt == qt);
        const int rowm = w * 16 + (lane >> 2);
        float tm0 = NEG_INF, tm1 = NEG_INF;
#pragma unroll
        for (int nt = 0; nt < 8; nt++) {
            const int cn = nt * 8 + (lane & 3) * 2;
            if (diag) {
                if (cn > rowm)         S[nt][0] = NEG_INF;
                if (cn + 1 > rowm)     S[nt][1] = NEG_INF;
                if (cn > rowm + 8)     S[nt][2] = NEG_INF;
                if (cn + 1 > rowm + 8) S[nt][3] = NEG_INF;
            }
            tm0 = fmaxf(tm0, fmaxf(S[nt][0], S[nt][1]));
            tm1 = fmaxf(tm1, fmaxf(S[nt][2], S[nt][3]));
        }
        tm0 = fmaxf(tm0, __shfl_xor_sync(0xffffffffu, tm0, 1));
        tm0 = fmaxf(tm0, __shfl_xor_sync(0xffffffffu, tm0, 2));
        tm1 = fmaxf(tm1, __shfl_xor_sync(0xffffffffu, tm1, 1));
        tm1 = fmaxf(tm1, __shfl_xor_sync(0xffffffffu, tm1, 2));

        const float mn0 = fmaxf(m0, tm0);
        const float mn1 = fmaxf(m1, tm1);
        const float a0 = __expf(m0 - mn0);
        const float a1 = __expf(m1 - mn1);

        float ps0 = 0.f, ps1 = 0.f;
#pragma unroll
        for (int nt = 0; nt < 8; nt++) {
            S[nt][0] = __expf(S[nt][0] - mn0);
            S[nt][1] = __expf(S[nt][1] - mn0);
            S[nt][2] = __expf(S[nt][2] - mn1);
            S[nt][3] = __expf(S[nt][3] - mn1);
            ps0 += S[nt][0] + S[nt][1];
            ps1 += S[nt][2] + S[nt][3];
        }
        ps0 += __shfl_xor_sync(0xffffffffu, ps0, 1);
        ps0 += __shfl_xor_sync(0xffffffffu, ps0, 2);
        ps1 += __shfl_xor_sync(0xffffffffu, ps1, 1);
        ps1 += __shfl_xor_sync(0xffffffffu, ps1, 2);
        l0 = l0 * a0 + ps0;
        l1 = l1 * a1 + ps1;
#pragma unroll
        for (int nt = 0; nt < 8; nt++) {
            O[nt][0] *= a0;
            O[nt][1] *= a0;
            O[nt][2] *= a1;
            O[nt][3] *= a1;
        }
        m0 = mn0;
        m1 = mn1;

        // O += P @ V (2 passes: P hi, P lo; V single)
#pragma unroll
        for (int kc = 0; kc < 4; kc++) {
            u32 ph[4], pl[4];
            split2h(S[2 * kc][0], S[2 * kc][1], &ph[0], &pl[0]);
            split2h(S[2 * kc][2], S[2 * kc][3], &ph[1], &pl[1]);
            split2h(S[2 * kc + 1][0], S[2 * kc + 1][1], &ph[2], &pl[2]);
            split2h(S[2 * kc + 1][2], S[2 * kc + 1][3], &ph[3], &pl[3]);
#pragma unroll
            for (int nt = 0; nt < 8; nt++) {
                u32 vb[2];
                const int rr = kc * 16 + (lane & 15);
                ldsm_x2t(vb, &sV[rr][nt * 8]);
                mma16816(O[nt], ph, vb);
                mma16816(O[nt], pl, vb);
            }
        }
    }

    // epilogue: normalize, split fp16 hi/lo, write [row][h*64+d]
    const float i0 = 1.0f / l0;
    const float i1 = 1.0f / l1;
    const int h = hb & (NH - 1);
    const int b = hb >> 4;
    const int s0 = q0 + w * 16 + (lane >> 2);
    const size_t r0 = (size_t)(b * SEQ + s0) * D_MODEL + h * DK + (lane & 3) * 2;
    const size_t r1 = r0 + 8ull * D_MODEL;
#pragma unroll
    for (int nt = 0; nt < 8; nt++) {
        u32 h2, l2;
        split2h(O[nt][0] * i0, O[nt][1] * i0, &h2, &l2);
        *(u32*)&ohi[r0 + nt * 8] = h2;
        *(u32*)&olo[r0 + nt * 8] = l2;
        split2h(O[nt][2] * i1, O[nt][3] * i1, &h2, &l2);
        *(u32*)&ohi[r1 + nt * 8] = h2;
        *(u32*)&olo[r1 + nt * 8] = l2;
    }
}

// ---------------------------------------------------------------------------
extern "C" void kernel_launch(void* const* d_in, const int* in_sizes, int n_in,
                              void* d_out, int out_size)
{
    const float* x  = (const float*)d_in[0];
    const float* Wq = (const float*)d_in[1];
    const float* Wk = (const float*)d_in[2];
    const float* Wv = (const float*)d_in[3];
    const float* Wo = (const float*)d_in[4];
    float* out = (float*)d_out;

    float* qkv = 0;
    cudaGetSymbolAddress((void**)&qkv, g_QKV);

    __half* xh = 0;
    __half* xl = 0;
    __half* ah = 0;
    __half* al = 0;
    __half* wh = 0;
    cudaGetSymbolAddress((void**)&xh, g_xh);
    cudaGetSymbolAddress((void**)&xl, g_xl);
    cudaGetSymbolAddress((void**)&ah, g_ah);
    cudaGetSymbolAddress((void**)&al, g_al);
    cudaGetSymbolAddress((void**)&wh, g_wh);

    __half* qh = 0;
    __half* ql = 0;
    __half* kh = 0;
    __half* vh = 0;
    cudaGetSymbolAddress((void**)&qh, g_qh);
    cudaGetSymbolAddress((void**)&ql, g_ql);
    cudaGetSymbolAddress((void**)&kh, g_kh);
    cudaGetSymbolAddress((void**)&vh, g_vh);

    const size_t WSZ = (size_t)D_MODEL * D_MODEL;
    const int wN4 = (int)(WSZ / 4);
    const int xN4 = M_ROWS * D_MODEL / 4;
    const int wBlocks = (wN4 + 255) / 256;
    const int xBlocks = (xN4 + 255) / 256;

    dim3 wgrid(wBlocks, 4);
    convert_w4<<<wgrid, 256>>>(Wq, Wk, Wv, Wo, wh, wN4);
    split_x<<<xBlocks, 256>>>(x, xh, xl, xN4);

    // fused QKV projection: [4096][3072] = x @ [Wq;Wk;Wv]^T
    dim3 gqkv(3 * D_MODEL / BN, M_ROWS / BM);       // (24, 32)
    gemm_2p<<<gqkv, 256>>>(xh, xl, wh, qkv, M_ROWS, 3 * D_MODEL, D_MODEL);

    int npairs = M_ROWS * (D_MODEL / 2);
    qkv_finish<<<(npairs + 255) / 256, 256>>>(qkv, qh, ql, kh, vh);

    dim3 agrid(SEQ / 64, NH * BATCH);               // (32, 32)
    attn_mma<<<agrid, 128>>>(qh, ql, kh, vh, ah, al);

    // output projection: [4096][1024] = attn @ Wo^T
    dim3 go(D_MODEL / BN, M_ROWS / BM);             // (8, 32)
    gemm_2p<<<go, 256>>>(ah, al, wh + 3 * WSZ, out, M_ROWS, D_MODEL, D_MODEL);
}